// round 11
// baseline (speedup 1.0000x reference)
#include <cuda_runtime.h>
#include <cuda_bf16.h>

// Full-occupancy persistent wave: 148 SMs x 8 blocks/SM (regs forced <=32)
static constexpr int WAVE_BLOCKS = 148 * 8;   // 1184
static constexpr int THREADS     = 256;
// Work unit: one chunk = THREADS quads (4 rows/thread)
static constexpr int CHUNK_QUADS = THREADS;

__device__ double        g_part[WAVE_BLOCKS];
__device__ unsigned int  g_chunk  = 0;        // work-stealing counter (self-reset)
__device__ unsigned int  g_ticket = 0;        // finish ticket (self-reset)

__device__ __forceinline__ float4 ldcs4(const float4* p) {
    return __ldcs(p);
}
__device__ __forceinline__ int4 ldcs4i(const int4* p) {
    return __ldcs(p);
}

__device__ __forceinline__ float row_term(float i0, float i1, float i2,
                                          int t0, int t1, int t2, int cs,
                                          const float* __restrict__ w,
                                          float invB) {
    // sample weight: class {100..700} -> index t2/100 - 1
    float sw = w[t2 / 100 - 1];
    float f0 = (float)t0, f1 = (float)t1, f2 = (float)t2;
    float d0 = i0 - f0, d1 = i1 - f1, d2 = i2 - f2;
    // sensors .mean(axis=1) -> 0.5*(d0^2+d1^2); anomaly -> d2^2; /B folded via invB
    float main_t = sw * (0.5f * (d0 * d0 + d1 * d1) + d2 * d2);

    // R02: lo = 6400 (state 4), 6000 (states 5-8), else 11500 ; hi = 12000
    float r02lo = (cs == 4) ? 6400.0f
                 : ((unsigned)(cs - 5) <= 3u ? 6000.0f : 11500.0f);
    // R03: lo = 2200 ; hi = 13000 (state 8) else 2500
    float r03hi = (cs == 8) ? 13000.0f : 2500.0f;

    float b0 = fminf(f0 - r02lo, 0.0f);
    float a0 = fmaxf(f0 - 12000.0f, 0.0f);
    float b1 = fminf(f1 - 2200.0f, 0.0f);
    float a1 = fmaxf(f1 - r03hi, 0.0f);
    float p = b0 * b0 + a0 * a0 + b1 * b1 + a1 * a1;

    return fmaf(main_t, invB, p);
}

__global__ void __launch_bounds__(THREADS, 8)
fused_loss_kernel(const float* __restrict__ inputs,
                  const int* __restrict__ targets,
                  const int* __restrict__ cycle_states,
                  const float* __restrict__ weights,
                  float* __restrict__ out,
                  int nrows) {
    __shared__ float w[7];
    __shared__ unsigned int s_chunk;
    if (threadIdx.x < 7) w[threadIdx.x] = weights[threadIdx.x];
    if (threadIdx.x == 0) s_chunk = atomicAdd(&g_chunk, 1u);  // first grab
    __syncthreads();

    const float invB = 1.0f / (float)nrows;
    const float4* __restrict__ in4 = (const float4*)inputs;
    const int4*   __restrict__ tg4 = (const int4*)targets;
    const int4*   __restrict__ cs4 = (const int4*)cycle_states;

    const int nquad   = nrows >> 2;               // 4 rows per quad
    const unsigned int nchunks = (unsigned)(nquad / CHUNK_QUADS);

    float acc = 0.0f;   // <= ~8 quads (32 rows) per thread: f32 safe
    unsigned int cur = s_chunk;
    while (cur < nchunks) {
        int q = (int)cur * CHUNK_QUADS + (int)threadIdx.x;

        // front-batched streaming loads for this chunk
        float4 ia = ldcs4(&in4[3 * q + 0]);
        float4 ib = ldcs4(&in4[3 * q + 1]);
        float4 ic = ldcs4(&in4[3 * q + 2]);
        int4   ta = ldcs4i(&tg4[3 * q + 0]);
        int4   tb = ldcs4i(&tg4[3 * q + 1]);
        int4   tc = ldcs4i(&tg4[3 * q + 2]);
        int4   cs = ldcs4i(&cs4[q]);

        // grab NEXT chunk early so the atomic latency hides behind compute
        __syncthreads();
        if (threadIdx.x == 0) s_chunk = atomicAdd(&g_chunk, 1u);

        // rows: (ia.x,ia.y,ia.z) (ia.w,ib.x,ib.y) (ib.z,ib.w,ic.x) (ic.y,ic.z,ic.w)
        acc += row_term(ia.x, ia.y, ia.z, ta.x, ta.y, ta.z, cs.x, w, invB)
             + row_term(ia.w, ib.x, ib.y, ta.w, tb.x, tb.y, cs.y, w, invB)
             + row_term(ib.z, ib.w, ic.x, tb.z, tb.w, tc.x, cs.z, w, invB)
             + row_term(ic.y, ic.z, ic.w, tc.y, tc.z, tc.w, cs.w, w, invB);

        __syncthreads();
        cur = s_chunk;
    }

    // intra-block reduce in double (f32 partials promoted here)
    double dacc = (double)acc;
    #pragma unroll
    for (int o = 16; o; o >>= 1)
        dacc += __shfl_down_sync(0xffffffffu, dacc, o);

    __shared__ double sm[8];
    if ((threadIdx.x & 31) == 0) sm[threadIdx.x >> 5] = dacc;
    __syncthreads();

    __shared__ bool s_last;
    if (threadIdx.x == 0) {
        double v = sm[0];
        #pragma unroll
        for (int i = 1; i < 8; i++) v += sm[i];
        g_part[blockIdx.x] = v;
        __threadfence();
        unsigned int t = atomicAdd(&g_ticket, 1u);
        s_last = (t == gridDim.x - 1);
        if (s_last) {
            g_ticket = 0;   // reset for next graph replay
            g_chunk  = 0;   // reset scheduler for next graph replay
        }
    }
    __syncthreads();

    // last block reduces all partials and writes the scalar
    if (s_last) {
        __threadfence();
        double v = 0.0;
        for (int i = threadIdx.x; i < (int)gridDim.x; i += THREADS)
            v += g_part[i];
        #pragma unroll
        for (int o = 16; o; o >>= 1)
            v += __shfl_down_sync(0xffffffffu, v, o);
        if ((threadIdx.x & 31) == 0) sm[threadIdx.x >> 5] = v;
        __syncthreads();
        if (threadIdx.x == 0) {
            double tot = sm[0];
            #pragma unroll
            for (int i = 1; i < 8; i++) tot += sm[i];
            out[0] = (float)tot;
        }
    }
}

extern "C" void kernel_launch(void* const* d_in, const int* in_sizes, int n_in,
                              void* d_out, int out_size) {
    const float* inputs       = (const float*)d_in[0];   // [B,3] f32
    const int*   targets      = (const int*)d_in[1];     // [B,3] i32
    const int*   cycle_states = (const int*)d_in[2];     // [B]   i32
    const float* weights      = (const float*)d_in[3];   // [7]   f32
    float* out = (float*)d_out;

    int nrows = in_sizes[0] / 3;  // 4,194,304

    int nquad  = nrows >> 2;
    int blocks = (nquad + THREADS - 1) / THREADS;
    if (blocks > WAVE_BLOCKS) blocks = WAVE_BLOCKS;  // one full wave @ 8 blocks/SM
    fused_loss_kernel<<<blocks, THREADS>>>(inputs, targets, cycle_states,
                                           weights, out, nrows);
}

// round 13
// speedup vs baseline: 1.1618x; 1.1618x over previous
#include <cuda_runtime.h>
#include <cuda_bf16.h>

static constexpr int THREADS       = 256;
static constexpr int BLOCKS_PER_SM = 8;
static constexpr int WAVE_BLOCKS   = 148 * BLOCKS_PER_SM;  // 1184
static constexpr int CHUNK_QUADS   = 64;                   // 256 rows / chunk
static constexpr int CHUNK_ROWS    = CHUNK_QUADS * 4;
static constexpr int STAGES        = 3;
static constexpr int IN_BYTES      = CHUNK_ROWS * 12;      // 3072
static constexpr int TG_BYTES      = CHUNK_ROWS * 12;      // 3072
static constexpr int CS_BYTES      = CHUNK_ROWS * 4;       // 1024

__device__ double        g_part[WAVE_BLOCKS];
__device__ unsigned int  g_ticket = 0;   // self-resetting, graph-replay safe

__device__ __forceinline__ void cp16(void* smem_dst, const void* gmem_src) {
    unsigned int sa = (unsigned int)__cvta_generic_to_shared(smem_dst);
    asm volatile("cp.async.cg.shared.global [%0], [%1], 16;" :: "r"(sa), "l"(gmem_src));
}
__device__ __forceinline__ void cp_commit() {
    asm volatile("cp.async.commit_group;");
}
__device__ __forceinline__ void cp_wait1() {
    asm volatile("cp.async.wait_group 1;");
}

__device__ __forceinline__ float row_term(float i0, float i1, float i2,
                                          int t0, int t1, int t2, int cs,
                                          const float* __restrict__ w,
                                          float invB) {
    float sw = w[t2 / 100 - 1];                 // class {100..700} -> idx
    float f0 = (float)t0, f1 = (float)t1, f2 = (float)t2;
    float d0 = i0 - f0, d1 = i1 - f1, d2 = i2 - f2;
    // sensors .mean(axis=1) -> 0.5*(d0^2+d1^2); anomaly -> d2^2; /B via invB
    float main_t = sw * (0.5f * (d0 * d0 + d1 * d1) + d2 * d2);

    // R02: lo = 6400 (state 4), 6000 (states 5-8), else 11500 ; hi = 12000
    float r02lo = (cs == 4) ? 6400.0f
                 : ((unsigned)(cs - 5) <= 3u ? 6000.0f : 11500.0f);
    // R03: lo = 2200 ; hi = 13000 (state 8) else 2500
    float r03hi = (cs == 8) ? 13000.0f : 2500.0f;

    float b0 = fminf(f0 - r02lo, 0.0f);
    float a0 = fmaxf(f0 - 12000.0f, 0.0f);
    float b1 = fminf(f1 - 2200.0f, 0.0f);
    float a1 = fmaxf(f1 - r03hi, 0.0f);
    float p = b0 * b0 + a0 * a0 + b1 * b1 + a1 * a1;

    return fmaf(main_t, invB, p);
}

__global__ void __launch_bounds__(THREADS, BLOCKS_PER_SM)
fused_loss_kernel(const float* __restrict__ inputs,
                  const int* __restrict__ targets,
                  const int* __restrict__ cycle_states,
                  const float* __restrict__ weights,
                  float* __restrict__ out,
                  int nrows) {
    // 3-stage pipeline buffers: [in 3072 | tg 3072 | cs 1024] per stage
    __shared__ __align__(16) unsigned char sbuf[STAGES][IN_BYTES + TG_BYTES + CS_BYTES];
    __shared__ float w[7];
    if (threadIdx.x < 7) w[threadIdx.x] = weights[threadIdx.x];

    const float invB = 1.0f / (float)nrows;
    const int nquad   = nrows >> 2;
    const int nchunks = nquad / CHUNK_QUADS;              // 16384 for B
    const int tid     = threadIdx.x;

    // number of chunks this block handles (grid-stride over chunks)
    int mycount = 0;
    if ((int)blockIdx.x < nchunks)
        mycount = (nchunks - (int)blockIdx.x + (int)gridDim.x - 1) / (int)gridDim.x;

    // issue one chunk's copies into stage s
    auto issue = [&](int s, int chunk) {
        const char* gin = (const char*)inputs      + (size_t)chunk * IN_BYTES;
        const char* gtg = (const char*)targets     + (size_t)chunk * TG_BYTES;
        const char* gcs = (const char*)cycle_states + (size_t)chunk * CS_BYTES;
        unsigned char* s_in = sbuf[s];
        unsigned char* s_tg = sbuf[s] + IN_BYTES;
        unsigned char* s_cs = sbuf[s] + IN_BYTES + TG_BYTES;
        if (tid < IN_BYTES / 16)  cp16(s_in + tid * 16, gin + tid * 16);   // 192 ops
        if (tid < TG_BYTES / 16)  cp16(s_tg + tid * 16, gtg + tid * 16);   // 192 ops
        if (tid < CS_BYTES / 16)  cp16(s_cs + tid * 16, gcs + tid * 16);   // 64 ops
    };

    // prologue: fill 2 stages
    for (int k = 0; k < 2; k++) {
        if (k < mycount) issue(k, (int)blockIdx.x + k * (int)gridDim.x);
        cp_commit();
    }

    float acc = 0.0f;   // ~14 rows/thread in f32: safe
    for (int k = 0; k < mycount; k++) {
        cp_wait1();          // stage k%3 complete (this thread's groups)
        __syncthreads();     // all threads' copies visible; prev consume done

        // refill: issue chunk k+2 into the stage freed at iteration k-1
        if (k + 2 < mycount) issue((k + 2) % STAGES, (int)blockIdx.x + (k + 2) * (int)gridDim.x);
        cp_commit();

        // consume stage k%3: thread handles row 'tid' of 256 rows
        const float* s_in = (const float*)(sbuf[k % STAGES]);
        const int*   s_tg = (const int*)(sbuf[k % STAGES] + IN_BYTES);
        const int*   s_cs = (const int*)(sbuf[k % STAGES] + IN_BYTES + TG_BYTES);
        float i0 = s_in[3 * tid + 0], i1 = s_in[3 * tid + 1], i2 = s_in[3 * tid + 2];
        int   t0 = s_tg[3 * tid + 0], t1 = s_tg[3 * tid + 1], t2 = s_tg[3 * tid + 2];
        int   cs = s_cs[tid];
        acc += row_term(i0, i1, i2, t0, t1, t2, cs, w, invB);
    }

    // tail rows (none for B=4M, but keep general): direct global loads
    int remstart = nchunks * CHUNK_ROWS;
    for (int r = remstart + (int)blockIdx.x * THREADS + tid; r < nrows;
         r += (int)gridDim.x * THREADS) {
        acc += row_term(inputs[3 * r], inputs[3 * r + 1], inputs[3 * r + 2],
                        targets[3 * r], targets[3 * r + 1], targets[3 * r + 2],
                        cycle_states[r], w, invB);
    }

    // intra-block reduce in double
    double dacc = (double)acc;
    #pragma unroll
    for (int o = 16; o; o >>= 1)
        dacc += __shfl_down_sync(0xffffffffu, dacc, o);

    __shared__ double sm[8];
    if ((tid & 31) == 0) sm[tid >> 5] = dacc;
    __syncthreads();

    __shared__ bool s_last;
    if (tid == 0) {
        double v = sm[0];
        #pragma unroll
        for (int i = 1; i < 8; i++) v += sm[i];
        g_part[blockIdx.x] = v;
        __threadfence();
        unsigned int t = atomicAdd(&g_ticket, 1u);
        s_last = (t == gridDim.x - 1);
        if (s_last) g_ticket = 0;   // reset for next graph replay
    }
    __syncthreads();

    if (s_last) {
        __threadfence();
        double v = 0.0;
        for (int i = tid; i < (int)gridDim.x; i += THREADS)
            v += g_part[i];
        #pragma unroll
        for (int o = 16; o; o >>= 1)
            v += __shfl_down_sync(0xffffffffu, v, o);
        if ((tid & 31) == 0) sm[tid >> 5] = v;
        __syncthreads();
        if (tid == 0) {
            double tot = sm[0];
            #pragma unroll
            for (int i = 1; i < 8; i++) tot += sm[i];
            out[0] = (float)tot;
        }
    }
}

extern "C" void kernel_launch(void* const* d_in, const int* in_sizes, int n_in,
                              void* d_out, int out_size) {
    const float* inputs       = (const float*)d_in[0];   // [B,3] f32
    const int*   targets      = (const int*)d_in[1];     // [B,3] i32
    const int*   cycle_states = (const int*)d_in[2];     // [B]   i32
    const float* weights      = (const float*)d_in[3];   // [7]   f32
    float* out = (float*)d_out;

    int nrows = in_sizes[0] / 3;  // 4,194,304

    int nquad  = nrows >> 2;
    int blocks = (nquad + THREADS - 1) / THREADS;
    if (blocks > WAVE_BLOCKS) blocks = WAVE_BLOCKS;
    fused_loss_kernel<<<blocks, THREADS>>>(inputs, targets, cycle_states,
                                           weights, out, nrows);
}